// round 14
// baseline (speedup 1.0000x reference)
#include <cuda_runtime.h>
#include <cuda_fp16.h>
#include <math.h>
#include <stdint.h>

#define B 256
#define T 512
#define F 128
#define H 256
#define H3 768
#define BH (B * H)

// Flag array for inter-block sync (one 128B line per flag)
#define NJB 8
#define NBB 16
__device__ unsigned g_flags[NBB][NJB * 32];

// fp16 h exchange buffer, double-buffered on t&1
__device__ __align__(16) half g_hbuf[2 * B * H];

// ---------------------------------------------------------------------------
// Helpers
// ---------------------------------------------------------------------------
__device__ __forceinline__ float tanh_fast(float x) {
    float y;
    asm("tanh.approx.f32 %0, %1;" : "=f"(y) : "f"(x));
    return y;
}
__device__ __forceinline__ float sig_fast(float x) {
    return fmaf(0.5f, tanh_fast(0.5f * x), 0.5f);
}
__device__ __forceinline__ unsigned ld_acq(const unsigned* p) {
    unsigned v;
    asm volatile("ld.acquire.gpu.global.u32 %0, [%1];" : "=r"(v) : "l"(p));
    return v;
}
__device__ __forceinline__ void st_rel(unsigned* p, unsigned v) {
    asm volatile("st.release.gpu.global.u32 [%0], %1;" :: "l"(p), "r"(v) : "memory");
}
__device__ __forceinline__ uint32_t pack_h2(float lo, float hi) {
    half2 h = __floats2half2_rn(lo, hi);
    return *reinterpret_cast<uint32_t*>(&h);
}
__device__ __forceinline__ uint32_t smem_u32(const void* p) {
    uint32_t a;
    asm("{ .reg .u64 t; cvta.to.shared.u64 t, %1; cvt.u32.u64 %0, t; }"
        : "=r"(a) : "l"(p));
    return a;
}
__device__ __forceinline__ void mma_f16(float* d,
                                        uint32_t a0, uint32_t a1, uint32_t a2, uint32_t a3,
                                        uint32_t b0, uint32_t b1) {
    asm volatile(
        "mma.sync.aligned.m16n8k16.row.col.f32.f16.f16.f32 "
        "{%0,%1,%2,%3}, {%4,%5,%6,%7}, {%8,%9}, {%0,%1,%2,%3};"
        : "+f"(d[0]), "+f"(d[1]), "+f"(d[2]), "+f"(d[3])
        : "r"(a0), "r"(a1), "r"(a2), "r"(a3), "r"(b0), "r"(b1));
}
__device__ __forceinline__ void ldsm_x4(uint32_t& a0, uint32_t& a1,
                                        uint32_t& a2, uint32_t& a3, uint32_t saddr) {
    asm volatile("ldmatrix.sync.aligned.m8n8.x4.shared.b16 {%0,%1,%2,%3}, [%4];"
                 : "=r"(a0), "=r"(a1), "=r"(a2), "=r"(a3) : "r"(saddr));
}

// ---------------------------------------------------------------------------
// Persistent fused GRU kernel (fp16 tensor cores, warp-specialized).
// Grid (8 j-tiles, 16 b-groups) = 128 blocks, 512 threads, 1 block/SM.
//
// Warps 0-11:  recurrence mh = h(t-1) @ Wr; ONE n8-chunk each (16 HMMA);
//              Wr frags in 32 regs; A frags via ldmatrix.x4.
//              Warps 0-6 also stage one peer h tile each (fp16 LDG from
//              g_hbuf, STS) with fused flag poll, before barA.
// Warps 12-15: input projection for t+1 (x stage + ldmatrix + 24 HMMA,
//              A frags reused over 3 n-chunks); mxs double-buffered.
// Phase C:     512 threads, 1 element; fp32 gates; STG g_hbuf (fp16) +
//              STS own hsh tile; barC; flag st.release; out STG AFTER flag.
// ---------------------------------------------------------------------------
#define BT 16
#define JT 32
#define HST 264                     // hs row stride in halves (528B: LDSM-clean)
#define XST 136                     // xs row stride in halves (272B)
#define PTS 100                     // mh tile row stride (f32)
#define MXS 100                     // mx tile row stride (f32)

#define HS_BYTES (BT * HST * 2)            // 8448
#define XS_BYTES (BT * XST * 2)            // 4352
#define PT_BYTES (BT * PTS * 4)            // 6400
#define MX_BYTES (2 * BT * MXS * 4)        // 12800
#define SMEM_BYTES (HS_BYTES + XS_BYTES + PT_BYTES + MX_BYTES)

extern __shared__ char smem_dyn[];

__global__ __launch_bounds__(512, 1)
void gru_persist(const float* __restrict__ x,
                 const float* __restrict__ wk,
                 const float* __restrict__ wr,
                 const float* __restrict__ bias,
                 float* __restrict__ out) {
    half*  hsh = (half*)(smem_dyn);                         // [16][HST]
    half*  xsh = (half*)(smem_dyn + HS_BYTES);              // [16][XST]
    float* pt  = (float*)(smem_dyn + HS_BYTES + XS_BYTES);  // [16][PTS]
    float* mxs = (float*)(smem_dyn + HS_BYTES + XS_BYTES + PT_BYTES); // [2][16][MXS]

    const int tid = (int)threadIdx.x;              // 0..511
    const int wid = tid >> 5;                      // 0..15
    const int lane = tid & 31;
    const int jb = (int)blockIdx.x;                // 0..7
    const int ib = (int)blockIdx.y;                // 0..15
    const int b0 = ib * BT;
    const int j0 = jb * JT;

    // mma fragment indices
    const int g8 = lane >> 2;                      // 0..7
    const int tg = lane & 3;                       // 0..3

    // ldmatrix per-lane row/koff
    const int lrow = (lane & 7) + ((lane >> 3) & 1) * 8;
    const int lkoff = (lane >> 4) * 8;
    const uint32_t hs_base = smem_u32(hsh) + (uint32_t)(lrow * HST + lkoff) * 2u;
    const uint32_t xs_base = smem_u32(xsh) + (uint32_t)(lrow * XST + lkoff) * 2u;

    // Phase-C mapping
    const int bc = tid >> 5;                       // 0..15
    const int jc = tid & 31;                       // 0..31

    // h stager mapping: warps 0-6 -> peers 1..7
    const int peer = (jb + 1 + wid) & 7;           // valid for wid<7

    // ---- Preload weight fragments into registers ----
    uint32_t bw[48];
    if (wid < 12) {
        // rec: one n8-chunk. gate = wid>>2, jj0 = (wid&3)*8
        const int gate = wid >> 2;
        const int jj0 = (wid & 3) * 8;
        const int col = gate * H + j0 + jj0 + g8;
        #pragma unroll
        for (int kc = 0; kc < 16; kc++) {
            const int kb = kc * 16;
            bw[2 * kc] =
                pack_h2(wr[(size_t)(kb + 2 * tg) * H3 + col],
                        wr[(size_t)(kb + 2 * tg + 1) * H3 + col]);
            bw[2 * kc + 1] =
                pack_h2(wr[(size_t)(kb + 2 * tg + 8) * H3 + col],
                        wr[(size_t)(kb + 2 * tg + 9) * H3 + col]);
        }
    } else {
        // proj: 3 n8-chunks, 8 kc each
        #pragma unroll
        for (int ci = 0; ci < 3; ci++) {
            const int cc = (wid - 12) * 3 + ci;
            const int gate = cc >> 2;
            const int jj0 = (cc & 3) * 8;
            const int col = gate * H + j0 + jj0 + g8;
            #pragma unroll
            for (int kc = 0; kc < 8; kc++) {
                const int kb = kc * 16;
                bw[ci * 16 + 2 * kc] =
                    pack_h2(wk[(size_t)(kb + 2 * tg) * H3 + col],
                            wk[(size_t)(kb + 2 * tg + 1) * H3 + col]);
                bw[ci * 16 + 2 * kc + 1] =
                    pack_h2(wk[(size_t)(kb + 2 * tg + 8) * H3 + col],
                            wk[(size_t)(kb + 2 * tg + 9) * H3 + col]);
            }
        }
    }

    // Biases (input + recurrent) for phase C
    const float bzi = bias[j0 + jc];
    const float bri = bias[H + jc + j0];
    const float bhi = bias[2 * H + j0 + jc];
    const float bzr = bias[H3 + j0 + jc];
    const float brr = bias[H3 + H + j0 + jc];
    const float bhr = bias[H3 + 2 * H + j0 + jc];

    // Zero hs (step 0 h = 0)
    for (int i = tid; i < BT * HST; i += 512) hsh[i] = __float2half_rn(0.0f);
    __syncthreads();

    float hp = 0.0f;                               // carried own h element

    for (int t = 0; t < T; t++) {
        if (wid >= 12) {
            // ===== PROJ (warps 12-15): mx_t this iter (t), pipelined =====
            // Note: computes mx for step t exactly at iter t's top; phase C
            // of iter t reads it after barA+barB. mx_t is independent of h.
            {
                // stage x_t tile: 16 rows x 32 f4, 128 threads -> 4 each
                const int pid = tid - 384;
                #pragma unroll
                for (int i = 0; i < 4; i++) {
                    int idx = pid + i * 128;
                    int row = idx >> 5, c4 = idx & 31;
                    float4 v = *(const float4*)
                        &x[((size_t)(b0 + row) * T + t) * F + c4 * 4];
                    uint2 u;
                    u.x = pack_h2(v.x, v.y);
                    u.y = pack_h2(v.z, v.w);
                    *(uint2*)&xsh[row * XST + c4 * 4] = u;
                }
                asm volatile("bar.sync 2, 128;" ::: "memory");
                // A frags once, reuse over 3 chunks
                uint32_t xa[8][4];
                #pragma unroll
                for (int kc = 0; kc < 8; kc++)
                    ldsm_x4(xa[kc][0], xa[kc][1], xa[kc][2], xa[kc][3],
                            xs_base + kc * 32);
                float* mxb = mxs + (t & 1) * (BT * MXS);
                #pragma unroll
                for (int ci = 0; ci < 3; ci++) {
                    const int cc = (wid - 12) * 3 + ci;
                    const int gate = cc >> 2;
                    const int jj0 = (cc & 3) * 8;
                    float d[4] = {};
                    #pragma unroll
                    for (int kc = 0; kc < 8; kc++)
                        mma_f16(d, xa[kc][0], xa[kc][1], xa[kc][2], xa[kc][3],
                                bw[ci * 16 + 2 * kc], bw[ci * 16 + 2 * kc + 1]);
                    float* mr0 = mxb + g8 * MXS + gate * 32 + jj0 + 2 * tg;
                    *(float2*)mr0 = make_float2(d[0], d[1]);
                    *(float2*)(mr0 + 8 * MXS) = make_float2(d[2], d[3]);
                }
            }
        } else if (wid < 7 && t > 0) {
            // ===== STAGERS (warps 0-6): poll + stage one peer h tile =====
            if (lane == 0) {
                const unsigned* fp = &g_flags[ib][peer * 32];
                while (ld_acq(fp) < (unsigned)t) { __nanosleep(20); }
            }
            __syncwarp();
            const half* hsrc = g_hbuf + (size_t)((t - 1) & 1) * BH;
            #pragma unroll
            for (int i = 0; i < 2; i++) {
                int idx = lane + i * 32;           // 16 rows x 4 uint4
                int row = idx >> 2, q = idx & 3;
                uint4 v = *(const uint4*)
                    &hsrc[(size_t)(b0 + row) * H + peer * 32 + q * 8];
                *(uint4*)&hsh[row * HST + peer * 32 + q * 8] = v;
            }
        }
        __syncthreads();   // barA: hs complete, mxs[t&1] complete

        // ===== REC (warps 0-11): mh = h(t-1) @ Wr, one n8-chunk =====
        if (wid < 12 && t > 0) {
            float d[4] = {};
            #pragma unroll
            for (int kc = 0; kc < 16; kc++) {
                uint32_t a0, a1, a2, a3;
                ldsm_x4(a0, a1, a2, a3, hs_base + kc * 32);
                mma_f16(d, a0, a1, a2, a3, bw[2 * kc], bw[2 * kc + 1]);
            }
            const int gate = wid >> 2;
            const int jj0 = (wid & 3) * 8;
            float* pr0 = pt + g8 * PTS + gate * 32 + jj0 + 2 * tg;
            *(float2*)pr0 = make_float2(d[0], d[1]);
            *(float2*)(pr0 + 8 * PTS) = make_float2(d[2], d[3]);
        }
        __syncthreads();   // barB: pt ready

        // ===== PHASE C: gates + publish (all 512 threads) =====
        float o;
        {
            const float* mrow = mxs + (t & 1) * (BT * MXS) + bc * MXS;
            float xz = mrow[jc] + bzi;
            float xr = mrow[32 + jc] + bri;
            float xh = mrow[64 + jc] + bhi;
            float mz = 0.f, mr = 0.f, mh = 0.f;
            if (t > 0) {
                const float* p = pt + bc * PTS + jc;
                mz = p[0];
                mr = p[32];
                mh = p[64];
            }
            float z = sig_fast(xz + mz + bzr);
            float r = sig_fast(xr + mr + brr);
            float c = tanh_fast(xh + r * (mh + bhr));
            o = c + z * (hp - c);
            half oh = __float2half_rn(o);
            g_hbuf[(size_t)(t & 1) * BH + (size_t)(b0 + bc) * H + j0 + jc] = oh;
            hsh[bc * HST + j0 + jc] = oh;          // own tile, no L2
            hp = o;
        }
        __syncthreads();   // barC: g_hbuf STGs + hsh STS ordered
        if (tid == 0) {
            st_rel(&g_flags[ib][jb * 32], (unsigned)(t + 1));
        }
        // fp32 output store: required result, but nothing reads it -> after flag
        out[(size_t)t * BH + (size_t)(b0 + bc) * H + j0 + jc] = o;
    }
}

// ---------------------------------------------------------------------------
// Launch
// ---------------------------------------------------------------------------
extern "C" void kernel_launch(void* const* d_in, const int* in_sizes, int n_in,
                              void* d_out, int out_size) {
    (void)in_sizes; (void)n_in; (void)out_size;
    const float* x    = (const float*)d_in[0];   // (B, T, F)
    const float* wk   = (const float*)d_in[1];   // (F, 3H)
    const float* wr   = (const float*)d_in[2];   // (H, 3H)
    const float* bias = (const float*)d_in[3];   // (2, 3H)
    float* out = (float*)d_out;                  // (T, B, H)

    static int attr_set = 0;
    if (!attr_set) {
        cudaFuncSetAttribute(gru_persist,
                             cudaFuncAttributeMaxDynamicSharedMemorySize,
                             SMEM_BYTES);
        attr_set = 1;
    }

    void* flags;
    cudaGetSymbolAddress(&flags, g_flags);
    cudaMemsetAsync(flags, 0, sizeof(unsigned) * NBB * NJB * 32, 0);

    dim3 g2(NJB, NBB);                           // (8, 16) = 128 blocks
    gru_persist<<<g2, 512, SMEM_BYTES>>>(x, wk, wr, bias, out);
}